// round 5
// baseline (speedup 1.0000x reference)
#include <cuda_runtime.h>
#include <cstdint>

#define BATCH 8
#define NTOK  4096
#define CIN   192
#define HID   768
#define EPSBN 1e-5f

#define XT_N (BATCH * NTOK * CIN)   // 6291456
#define W_N  (HID * CIN)            // 147456

// Scratch
__device__ float  g_ht[(size_t)BATCH * HID * NTOK];   // hidden, [B,H,N], ~100.7MB
__device__ float  g_xt[XT_N];                         // tf32-rounded x
__device__ float  g_w1t[W_N];                         // tf32-rounded W1
__device__ float  g_w2t[W_N];                         // tf32-rounded W2
__device__ float2 g_tw[NTOK];                         // forward twiddles

// padded smem index for FFT buffers
#define PAD(i) ((i) + ((i) >> 5))
#define FFT_BUF 4224

// ---------------------------------------------------------------------------
__device__ __forceinline__ float tf32r(float x)
{
    uint32_t r;
    asm("cvt.rna.tf32.f32 %0, %1;" : "=r"(r) : "f"(x));
    return __uint_as_float(r);
}

__device__ __forceinline__ void mma_tf32(float4& d, const uint32_t* a, const uint32_t* b)
{
    asm volatile(
        "mma.sync.aligned.m16n8k8.row.col.f32.tf32.tf32.f32 "
        "{%0,%1,%2,%3}, {%4,%5,%6,%7}, {%8,%9}, {%0,%1,%2,%3};"
        : "+f"(d.x), "+f"(d.y), "+f"(d.z), "+f"(d.w)
        : "r"(a[0]), "r"(a[1]), "r"(a[2]), "r"(a[3]), "r"(b[0]), "r"(b[1]));
}

__device__ __forceinline__ void cp_async16(uint32_t saddr, const void* gptr)
{
    asm volatile("cp.async.cg.shared.global [%0], [%1], 16;" :: "r"(saddr), "l"(gptr));
}
#define CP_COMMIT() asm volatile("cp.async.commit_group;")
#define CP_WAIT1()  asm volatile("cp.async.wait_group 1;")

// ---------------------------------------------------------------------------
__global__ void twiddle_init_k()
{
    int t = blockIdx.x * blockDim.x + threadIdx.x;
    if (t < NTOK) {
        float s, c;
        sincospif(-2.0f * (float)t / (float)NTOK, &s, &c);
        g_tw[t] = make_float2(c, s);
    }
}

// RN-round inputs to tf32 once (so GEMMs can feed raw bits losslessly)
__global__ void prep_k(const float* __restrict__ x, const float* __restrict__ W1,
                       const float* __restrict__ W2)
{
    int idx = blockIdx.x * blockDim.x + threadIdx.x;   // float4 index
    const float4* src;
    float4* dst;
    int off;
    if (idx < XT_N / 4)                 { src = (const float4*)x;  dst = (float4*)g_xt;  off = idx; }
    else if (idx < (XT_N + W_N) / 4)    { src = (const float4*)W1; dst = (float4*)g_w1t; off = idx - XT_N / 4; }
    else                                { src = (const float4*)W2; dst = (float4*)g_w2t; off = idx - (XT_N + W_N) / 4; }
    float4 v = src[off];
    v.x = tf32r(v.x); v.y = tf32r(v.y); v.z = tf32r(v.z); v.w = tf32r(v.w);
    dst[off] = v;
}

// ---------------------------------------------------------------------------
// GEMM1 (tf32, cp.async 3-stage): ht[b,h,n] = relu(BN( sum_c x[b,n,c]*W1[h,c] ))
// ---------------------------------------------------------------------------
#define G1_SSZ (128 * 20 * 2)
#define G1_SMEM (3 * G1_SSZ * 4)

__global__ __launch_bounds__(256) void gemm1_k(
    const float* __restrict__ g1, const float* __restrict__ b1,
    const float* __restrict__ m1, const float* __restrict__ v1)
{
    extern __shared__ uint32_t smem_u[];

    int tid  = threadIdx.x;
    int lane = tid & 31;
    int wid  = tid >> 5;
    int wm   = wid & 1;
    int wn   = wid >> 1;
    int lk   = lane & 3;
    int lg   = lane >> 2;

    int n0 = blockIdx.x * 128;
    int h0 = blockIdx.y * 128;
    int b  = blockIdx.z;

    const float* wp = g_w1t + (size_t)h0 * CIN;
    const float* xp = g_xt + ((size_t)b * NTOK + n0) * CIN;

    uint32_t sbase = (uint32_t)__cvta_generic_to_shared(smem_u);

    int lrow = tid >> 2;
    int lko  = (tid & 3) << 2;

#define G1_LOAD(st, kc)                                                          \
    {                                                                            \
        uint32_t ao = sbase + (st) * G1_SSZ * 4;                                 \
        uint32_t bo = ao + 128 * 20 * 4;                                         \
        _Pragma("unroll")                                                        \
        for (int i = 0; i < 2; i++) {                                            \
            int row = lrow + i * 64;                                             \
            cp_async16(ao + (row * 20 + lko) * 4, wp + (size_t)row * CIN + (kc) * 16 + lko); \
            cp_async16(bo + (row * 20 + lko) * 4, xp + (size_t)row * CIN + (kc) * 16 + lko); \
        }                                                                        \
    }

    float4 acc[4][4];
#pragma unroll
    for (int i = 0; i < 4; i++)
#pragma unroll
        for (int j = 0; j < 4; j++) acc[i][j] = make_float4(0.f, 0.f, 0.f, 0.f);

    G1_LOAD(0, 0); CP_COMMIT();
    G1_LOAD(1, 1); CP_COMMIT();

    for (int kc = 0; kc < 12; kc++) {
        CP_WAIT1();
        __syncthreads();
        if (kc + 2 < 12) { G1_LOAD((kc + 2) % 3, kc + 2); }
        CP_COMMIT();

        const uint32_t* sA = smem_u + (kc % 3) * G1_SSZ;
        const uint32_t* sB = sA + 128 * 20;
#pragma unroll
        for (int k0 = 0; k0 < 16; k0 += 8) {
            uint32_t afr[4][4], bfr[4][2];
#pragma unroll
            for (int mf = 0; mf < 4; mf++) {
                int mb = wm * 64 + mf * 16 + lg;
                afr[mf][0] = sA[(mb    ) * 20 + k0 + lk    ];
                afr[mf][1] = sA[(mb + 8) * 20 + k0 + lk    ];
                afr[mf][2] = sA[(mb    ) * 20 + k0 + lk + 4];
                afr[mf][3] = sA[(mb + 8) * 20 + k0 + lk + 4];
            }
#pragma unroll
            for (int nf = 0; nf < 4; nf++) {
                int nb = wn * 32 + nf * 8 + lg;
                bfr[nf][0] = sB[nb * 20 + k0 + lk    ];
                bfr[nf][1] = sB[nb * 20 + k0 + lk + 4];
            }
#pragma unroll
            for (int mf = 0; mf < 4; mf++)
#pragma unroll
                for (int nf = 0; nf < 4; nf++)
                    mma_tf32(acc[mf][nf], afr[mf], bfr[nf]);
        }
    }

#pragma unroll
    for (int mf = 0; mf < 4; mf++) {
        int h_r0 = h0 + wm * 64 + mf * 16 + lg;
        int h_r1 = h_r0 + 8;
        float sc0 = g1[h_r0] * rsqrtf(v1[h_r0] + EPSBN);
        float sh0 = b1[h_r0] - m1[h_r0] * sc0;
        float sc1 = g1[h_r1] * rsqrtf(v1[h_r1] + EPSBN);
        float sh1 = b1[h_r1] - m1[h_r1] * sc1;
        float* p0 = g_ht + ((size_t)(b * HID + h_r0)) * NTOK + n0;
        float* p1 = g_ht + ((size_t)(b * HID + h_r1)) * NTOK + n0;
#pragma unroll
        for (int nf = 0; nf < 4; nf++) {
            int nc = wn * 32 + nf * 8 + 2 * lk;
            float4 a = acc[mf][nf];
            float2 o0, o1;
            o0.x = fmaxf(fmaf(a.x, sc0, sh0), 0.0f);
            o0.y = fmaxf(fmaf(a.y, sc0, sh0), 0.0f);
            o1.x = fmaxf(fmaf(a.z, sc1, sh1), 0.0f);
            o1.y = fmaxf(fmaf(a.w, sc1, sh1), 0.0f);
            *(float2*)(p0 + nc) = o0;
            *(float2*)(p1 + nc) = o1;
        }
    }
}

// ---------------------------------------------------------------------------
// Fused FFT -> pointwise -> IFFT. Radix-16 Stockham, 3 stages (4096 = 16^3).
// 16-point FFT per thread in registers (two radix-4 levels + w16 twiddles).
// ---------------------------------------------------------------------------
__device__ __forceinline__ float2 cmulf(float2 a, float2 b)
{
    return make_float2(fmaf(a.x, b.x, -a.y * b.y), fmaf(a.x, b.y, a.y * b.x));
}

template <bool INV>
__device__ __forceinline__ void r4(float2 a0, float2 a1, float2 a2, float2 a3,
                                   float2& X0, float2& X1, float2& X2, float2& X3)
{
    float2 t0 = make_float2(a0.x + a2.x, a0.y + a2.y);
    float2 t1 = make_float2(a0.x - a2.x, a0.y - a2.y);
    float2 t2 = make_float2(a1.x + a3.x, a1.y + a3.y);
    float2 u  = make_float2(a1.x - a3.x, a1.y - a3.y);
    float2 t3 = INV ? make_float2(-u.y, u.x) : make_float2(u.y, -u.x);
    X0 = make_float2(t0.x + t2.x, t0.y + t2.y);
    X1 = make_float2(t1.x + t3.x, t1.y + t3.y);
    X2 = make_float2(t0.x - t2.x, t0.y - t2.y);
    X3 = make_float2(t1.x - t3.x, t1.y - t3.y);
}

// w16^T (forward: exp(-2*pi*i*T/16)); INV conjugates.
template <int T, bool INV>
__device__ __forceinline__ float2 w16mul(float2 v)
{
    constexpr float C1 = 0.92387953251128674f, S1 = 0.38268343236508978f;
    constexpr float C2 = 0.70710678118654752f;
    float c, s;
    if      (T == 0) return v;
    else if (T == 1) { c = C1;  s = S1; }
    else if (T == 2) { c = C2;  s = C2; }
    else if (T == 3) { c = S1;  s = C1; }
    else if (T == 4) { c = 0.f; s = 1.f; }
    else if (T == 6) { c = -C2; s = C2; }
    else             { c = -C1; s = -S1; }   // T == 9
    float si = INV ? s : -s;
    return cmulf(make_float2(c, si), v);
}

template <bool INV, int NS>
__device__ __forceinline__ void fft16_stage(const float2* __restrict__ src,
                                            float2* __restrict__ dst)
{
    int j = threadIdx.x;                // 0..255
    int k = j & (NS - 1);
    float2 a[16];
#pragma unroll
    for (int p = 0; p < 16; p++) a[p] = src[PAD(j + p * 256)];

    if (NS > 1) {
        int kk = k * (256 / NS);
#pragma unroll
        for (int p = 1; p < 16; p++) {
            float2 w = g_tw[p * kk];
            if (INV) w.y = -w.y;
            a[p] = cmulf(w, a[p]);
        }
    }

    // 16-pt FFT: p = p0 + 4*p1 ; A[q0 + 4*q1]
    float2 bq[4][4];                    // bq[p0][q0]
#pragma unroll
    for (int p0 = 0; p0 < 4; p0++)
        r4<INV>(a[p0], a[p0 + 4], a[p0 + 8], a[p0 + 12],
                bq[p0][0], bq[p0][1], bq[p0][2], bq[p0][3]);

    float2 A[16];
    // q0 = 0 (no w16 twiddles)
    r4<INV>(bq[0][0], bq[1][0], bq[2][0], bq[3][0], A[0], A[4], A[8],  A[12]);
    // q0 = 1: twiddles w16^{1,2,3}
    r4<INV>(bq[0][1], w16mul<1, INV>(bq[1][1]), w16mul<2, INV>(bq[2][1]),
            w16mul<3, INV>(bq[3][1]), A[1], A[5], A[9],  A[13]);
    // q0 = 2: twiddles w16^{2,4,6}
    r4<INV>(bq[0][2], w16mul<2, INV>(bq[1][2]), w16mul<4, INV>(bq[2][2]),
            w16mul<6, INV>(bq[3][2]), A[2], A[6], A[10], A[14]);
    // q0 = 3: twiddles w16^{3,6,9}
    r4<INV>(bq[0][3], w16mul<3, INV>(bq[1][3]), w16mul<6, INV>(bq[2][3]),
            w16mul<9, INV>(bq[3][3]), A[3], A[7], A[11], A[15]);

    int base = ((j - k) << 4) + k;
#pragma unroll
    for (int q = 0; q < 16; q++) dst[PAD(base + q * NS)] = A[q];
    __syncthreads();
}

template <bool INV>
__device__ __forceinline__ void fft4096(float2* bsrc, float2* bdst)
{
    // bsrc -> bdst -> bsrc -> bdst (result ends in bdst)
    fft16_stage<INV, 1>(bsrc, bdst);
    fft16_stage<INV, 16>(bdst, bsrc);
    fft16_stage<INV, 256>(bsrc, bdst);
}

__device__ __forceinline__ float2 pointwise(float2 X, float ra, float ia,
                                            float rbv, float ibv)
{
    float xr = fmaxf(fmaf(ra, X.x, fmaf(-ia, X.y, rbv)), 0.0f);
    float xi = fmaxf(fmaf(ra, X.y, fmaf(ia, X.x, ibv)), 0.0f);
    return make_float2(xr, xi);
}

__global__ __launch_bounds__(256, 1) void fftmix_k(
    const float* __restrict__ rmat, const float* __restrict__ imat,
    const float* __restrict__ rb,   const float* __restrict__ ib)
{
    extern __shared__ float2 sb[];
    float2* b0 = sb;
    float2* b1 = sb + FFT_BUF;

    int blk = blockIdx.x;
    int b   = blk / (HID / 2);
    int hp  = blk % (HID / 2);
    int h0  = 2 * hp;
    int h1  = h0 + 1;
    float* row0 = g_ht + ((size_t)(b * HID + h0)) * NTOK;
    float* row1 = row0 + NTOK;
    int tid = threadIdx.x;

    // pack two real rows as one complex row
#pragma unroll
    for (int q = 0; q < 16; q++) {
        int t = tid + q * 256;
        b0[PAD(t)] = make_float2(row0[t], row1[t]);
    }
    __syncthreads();

    fft4096<false>(b0, b1);             // Z ends in b1

    float ra0 = rmat[(size_t)h0 * HID + h0];
    float ia0 = imat[(size_t)h0 * HID + h0];
    float ra1 = rmat[(size_t)h1 * HID + h1];
    float ia1 = imat[(size_t)h1 * HID + h1];
    float rb0 = rb[h0], ib0 = ib[h0];
    float rb1 = rb[h1], ib1 = ib[h1];
    const float inv = 0.015625f;        // 1/sqrt(4096)

    // unpack -> pointwise -> Hermitian-project -> repack, pairwise (k, N-k)
    for (int p = tid; p < 2048; p += 256) {
        int k = p;
        int m = (NTOK - p) & (NTOK - 1);
#pragma unroll
        for (int rep = 0; rep < 2; rep++) {
            if (rep == 1) {
                if (p != 0) break;
                k = 2048; m = 2048;
            }
            float2 Zk = b1[PAD(k)];
            float2 Zm = b1[PAD(m)];
            float hv = 0.5f * inv;
            float2 X0k = make_float2((Zk.x + Zm.x) * hv, (Zk.y - Zm.y) * hv);
            float2 X1k = make_float2((Zk.y + Zm.y) * hv, (Zm.x - Zk.x) * hv);
            float2 X0m = make_float2((Zm.x + Zk.x) * hv, (Zm.y - Zk.y) * hv);
            float2 X1m = make_float2((Zm.y + Zk.y) * hv, (Zk.x - Zm.x) * hv);

            float2 S0k = pointwise(X0k, ra0, ia0, rb0, ib0);
            float2 S0m = pointwise(X0m, ra0, ia0, rb0, ib0);
            float2 S1k = pointwise(X1k, ra1, ia1, rb1, ib1);
            float2 S1m = pointwise(X1m, ra1, ia1, rb1, ib1);

            float2 H0 = make_float2(0.5f * (S0k.x + S0m.x), 0.5f * (S0k.y - S0m.y));
            float2 H1 = make_float2(0.5f * (S1k.x + S1m.x), 0.5f * (S1k.y - S1m.y));
            b1[PAD(k)] = make_float2(H0.x - H1.y, H0.y + H1.x);
            if (m != k)
                b1[PAD(m)] = make_float2(H0.x + H1.y, H1.x - H0.y);
        }
    }
    __syncthreads();

    fft4096<true>(b1, b0);              // y0 + i*y1 ends in b0

#pragma unroll
    for (int q = 0; q < 16; q++) {
        int t = tid + q * 256;
        float2 v = b0[PAD(t)];
        row0[t] = tf32r(v.x * inv);     // pre-round for GEMM2's tf32 A operand
        row1[t] = tf32r(v.y * inv);
    }
}

// ---------------------------------------------------------------------------
// GEMM2 (tf32, cp.async 3-stage): y[b,n,c] = BN( sum_h ht[b,h,n] * W2[c,h] )
// ---------------------------------------------------------------------------
#define G2_ASZ (16 * 264)
#define G2_WSZ (64 * 20)
#define G2_SSZ (G2_ASZ + G2_WSZ)
#define G2_SMEM (3 * G2_SSZ * 4)

__global__ __launch_bounds__(256) void gemm2_k(
    const float* __restrict__ g2, const float* __restrict__ b2,
    const float* __restrict__ m2, const float* __restrict__ v2,
    float* __restrict__ y)
{
    extern __shared__ uint32_t smem_u[];

    int tid  = threadIdx.x;
    int lane = tid & 31;
    int wid  = tid >> 5;
    int wm   = wid >> 1;
    int wn   = wid & 1;
    int lk   = lane & 3;
    int lg   = lane >> 2;

    int n0 = blockIdx.x * 256;
    int c0 = blockIdx.y * 64;
    int b  = blockIdx.z;

    const float* hp = g_ht + (size_t)b * HID * NTOK + n0;
    const float* wp = g_w2t + (size_t)c0 * HID;

    uint32_t sbase = (uint32_t)__cvta_generic_to_shared(smem_u);

    int arow = tid >> 6;
    int aoff = (tid & 63) << 2;
    int wrow = tid >> 2;
    int woff = (tid & 3) << 2;

#define G2_LOAD(st, kc)                                                          \
    {                                                                            \
        uint32_t ao = sbase + (st) * G2_SSZ * 4;                                 \
        uint32_t wo = ao + G2_ASZ * 4;                                           \
        _Pragma("unroll")                                                        \
        for (int i = 0; i < 4; i++) {                                            \
            int row = arow + i * 4;                                              \
            cp_async16(ao + (row * 264 + aoff) * 4,                              \
                       hp + (size_t)((kc) * 16 + row) * NTOK + aoff);            \
        }                                                                        \
        cp_async16(wo + (wrow * 20 + woff) * 4,                                  \
                   wp + (size_t)wrow * HID + (kc) * 16 + woff);                  \
    }

    float4 acc[4][4];
#pragma unroll
    for (int i = 0; i < 4; i++)
#pragma unroll
        for (int j = 0; j < 4; j++) acc[i][j] = make_float4(0.f, 0.f, 0.f, 0.f);

    G2_LOAD(0, 0); CP_COMMIT();
    G2_LOAD(1, 1); CP_COMMIT();

    for (int kc = 0; kc < 48; kc++) {
        CP_WAIT1();
        __syncthreads();
        if (kc + 2 < 48) { G2_LOAD((kc + 2) % 3, kc + 2); }
        CP_COMMIT();

        const uint32_t* sA = smem_u + (kc % 3) * G2_SSZ;
        const uint32_t* sW = sA + G2_ASZ;
#pragma unroll
        for (int k0 = 0; k0 < 16; k0 += 8) {
            uint32_t afr[4][4], bfr[4][2];
#pragma unroll
            for (int mf = 0; mf < 4; mf++) {
                int mb = wm * 64 + mf * 16 + lg;
                afr[mf][0] = sA[(k0 + lk    ) * 264 + mb    ];
                afr[mf][1] = sA[(k0 + lk    ) * 264 + mb + 8];
                afr[mf][2] = sA[(k0 + lk + 4) * 264 + mb    ];
                afr[mf][3] = sA[(k0 + lk + 4) * 264 + mb + 8];
            }
#pragma unroll
            for (int nf = 0; nf < 4; nf++) {
                int cb = wn * 32 + nf * 8 + lg;
                bfr[nf][0] = sW[cb * 20 + k0 + lk    ];
                bfr[nf][1] = sW[cb * 20 + k0 + lk + 4];
            }
#pragma unroll
            for (int mf = 0; mf < 4; mf++)
#pragma unroll
                for (int nf = 0; nf < 4; nf++)
                    mma_tf32(acc[mf][nf], afr[mf], bfr[nf]);
        }
    }

    float scv[4][2], shv[4][2];
#pragma unroll
    for (int nf = 0; nf < 4; nf++) {
        int c = c0 + wn * 32 + nf * 8 + 2 * lk;
#pragma unroll
        for (int j = 0; j < 2; j++) {
            scv[nf][j] = g2[c + j] * rsqrtf(v2[c + j] + EPSBN);
            shv[nf][j] = b2[c + j] - m2[c + j] * scv[nf][j];
        }
    }
#pragma unroll
    for (int mf = 0; mf < 4; mf++) {
        int n_r0 = n0 + wm * 64 + mf * 16 + lg;
        int n_r1 = n_r0 + 8;
        float* p0 = y + ((size_t)(b * NTOK + n_r0)) * CIN;
        float* p1 = y + ((size_t)(b * NTOK + n_r1)) * CIN;
#pragma unroll
        for (int nf = 0; nf < 4; nf++) {
            int c = c0 + wn * 32 + nf * 8 + 2 * lk;
            float4 a = acc[mf][nf];
            float2 o0, o1;
            o0.x = fmaf(a.x, scv[nf][0], shv[nf][0]);
            o0.y = fmaf(a.y, scv[nf][1], shv[nf][1]);
            o1.x = fmaf(a.z, scv[nf][0], shv[nf][0]);
            o1.y = fmaf(a.w, scv[nf][1], shv[nf][1]);
            *(float2*)(p0 + c) = o0;
            *(float2*)(p1 + c) = o1;
        }
    }
}

// ---------------------------------------------------------------------------
extern "C" void kernel_launch(void* const* d_in, const int* in_sizes, int n_in,
                              void* d_out, int out_size)
{
    const float* x  = (const float*)d_in[0];
    const float* W1 = (const float*)d_in[1];
    const float* g1 = (const float*)d_in[2];
    const float* b1 = (const float*)d_in[3];
    const float* m1 = (const float*)d_in[4];
    const float* v1 = (const float*)d_in[5];
    const float* r  = (const float*)d_in[6];
    const float* im = (const float*)d_in[7];
    const float* rb = (const float*)d_in[8];
    const float* ib = (const float*)d_in[9];
    const float* W2 = (const float*)d_in[10];
    const float* g2 = (const float*)d_in[11];
    const float* b2 = (const float*)d_in[12];
    const float* m2 = (const float*)d_in[13];
    const float* v2 = (const float*)d_in[14];
    float* y = (float*)d_out;

    static bool attr_set = false;
    if (!attr_set) {
        cudaFuncSetAttribute(fftmix_k, cudaFuncAttributeMaxDynamicSharedMemorySize,
                             2 * FFT_BUF * sizeof(float2));
        cudaFuncSetAttribute(gemm1_k, cudaFuncAttributeMaxDynamicSharedMemorySize, G1_SMEM);
        cudaFuncSetAttribute(gemm2_k, cudaFuncAttributeMaxDynamicSharedMemorySize, G2_SMEM);
        attr_set = true;
    }

    prep_k<<<(XT_N + 2 * W_N) / 4 / 256, 256>>>(x, W1, W2);
    twiddle_init_k<<<16, 256>>>();
    gemm1_k<<<dim3(NTOK / 128, HID / 128, BATCH), 256, G1_SMEM>>>(g1, b1, m1, v1);
    fftmix_k<<<BATCH * (HID / 2), 256, 2 * FFT_BUF * sizeof(float2)>>>(r, im, rb, ib);
    gemm2_k<<<dim3(NTOK / 256, CIN / 64, BATCH), 256, G2_SMEM>>>(g2, b2, m2, v2, y);
}